// round 14
// baseline (speedup 1.0000x reference)
#include <cuda_runtime.h>
#include <cuda_bf16.h>
#include <cstdint>
#include <math.h>

#define PTOT     110592            // 48^3
#define PHALF    (PTOT / 2)        // 55296
#define NDIR     32
#define NRES     64
#define PCHUNK   192
#define NCHK     (PHALF / PCHUNK)  // 288
#define NBLK_B   (NCHK * 4)        // 1152 (4 d-groups of 8 warps)
#define NBLK_A   (PTOT / 256)      // 432; blocks >= 216 are all-second-half
#define NE       (4 * NDIR * NRES) // 8192 floats

// ---------------- device scratch (static; no allocations) -------------------
__device__ float         g_E[NE];             // [(b*2+c)][d][r]
__device__ unsigned int  g_done;
__device__ float4        g_Cpart[216];        // per-block sums of dw, 2nd half
__device__ ulonglong2    g_dwd0[PTOT];        // p<half: (dup b0c0, dup b0c1)
__device__ ulonglong2    g_dwd1[PTOT];        // p<half: (dup b1c0, dup b1c1)
__device__ ulonglong2    g_dwn0[PTOT];        // p>=half: NEGATED dups
__device__ ulonglong2    g_dwn1[PTOT];
__device__ float         g_eb[NDIR * PHALF];  // eb[d][p] = exp(8*<coord_p,dir_d>)

// ---------------- asm helpers ------------------------------------------------
__device__ __forceinline__ unsigned long long pack2(float lo, float hi) {
    unsigned long long r;
    asm("mov.b64 %0, {%1, %2};" : "=l"(r) : "f"(lo), "f"(hi));
    return r;
}
__device__ __forceinline__ void unpack2(unsigned long long v, float& lo, float& hi) {
    asm("mov.b64 {%0, %1}, %2;" : "=f"(lo), "=f"(hi) : "l"(v));
}
__device__ __forceinline__ void fma2(unsigned long long& acc, unsigned long long ab,
                                     unsigned long long c) {
    asm("fma.rn.f32x2 %0, %1, %2, %0;" : "+l"(acc) : "l"(ab), "l"(c));
}
__device__ __forceinline__ float rcp_approx(float x) {
    float r;
    asm("rcp.approx.f32 %0, %1;" : "=f"(r) : "f"(x));
    return r;
}
__device__ __forceinline__ float ex2_approx(float x) {
    float r;
    asm("ex2.approx.f32 %0, %1;" : "=f"(r) : "f"(x));
    return r;
}

// ---------------- threefry2x32 (JAX partitionable path) ---------------------
__device__ __forceinline__ uint32_t rotl32(uint32_t x, int d) {
    return (x << d) | (x >> (32 - d));
}
__device__ void threefry2x32(uint32_t k0, uint32_t k1, uint32_t& x0, uint32_t& x1) {
    uint32_t k2 = k0 ^ k1 ^ 0x1BD11BDAu;
    x0 += k0; x1 += k1;
#define TFR(r) { x0 += x1; x1 = rotl32(x1, r); x1 ^= x0; }
    TFR(13) TFR(15) TFR(26) TFR(6)
    x0 += k1; x1 += k2 + 1u;
    TFR(17) TFR(29) TFR(16) TFR(24)
    x0 += k2; x1 += k0 + 2u;
    TFR(13) TFR(15) TFR(26) TFR(6)
    x0 += k0; x1 += k1 + 3u;
    TFR(17) TFR(29) TFR(16) TFR(24)
    x0 += k1; x1 += k2 + 4u;
    TFR(13) TFR(15) TFR(26) TFR(6)
    x0 += k2; x1 += k0 + 5u;
#undef TFR
}

__device__ float erfinv_f32(float x) {
    float w = -log1pf(-x * x);
    float p;
    if (w < 5.0f) {
        w = w - 2.5f;
        p =            2.81022636e-08f;
        p = fmaf(p, w, 3.43273939e-07f);
        p = fmaf(p, w, -3.5233877e-06f);
        p = fmaf(p, w, -4.39150654e-06f);
        p = fmaf(p, w, 0.00021858087f);
        p = fmaf(p, w, -0.00125372503f);
        p = fmaf(p, w, -0.00417768164f);
        p = fmaf(p, w, 0.246640727f);
        p = fmaf(p, w, 1.50140941f);
    } else {
        w = sqrtf(w) - 3.0f;
        p =            -0.000200214257f;
        p = fmaf(p, w, 0.000100950558f);
        p = fmaf(p, w, 0.00134934322f);
        p = fmaf(p, w, -0.00367342844f);
        p = fmaf(p, w, 0.00573950773f);
        p = fmaf(p, w, -0.0076224613f);
        p = fmaf(p, w, 0.00943887047f);
        p = fmaf(p, w, 1.00167406f);
        p = fmaf(p, w, 2.83297682f);
    }
    return p * x;
}

// ---------------- kernel A: init + prep + eb (first half only) --------------
__global__ __launch_bounds__(256) void kernelA(const float* __restrict__ pred,
                                               const void* __restrict__ tgt) {
    __shared__ float  sv[96];
    __shared__ float  sd[96];
    __shared__ int    s_t64;
    __shared__ float4 s_red[256];
    int tid = threadIdx.x;

    if (tid == 0) {
        // int64 targets (values 0..2, little-endian): odd 32-bit words all 0
        const int* ti = (const int*)tgt;
        int all0 = 1;
        for (int q = 0; q < 64; q++)
            if (ti[2 * q + 1] != 0) { all0 = 0; break; }
        s_t64 = all0;
    }
    if (tid < 96) {
        uint32_t x0 = 0u, x1 = (uint32_t)tid;
        threefry2x32(0u, 17u, x0, x1);
        uint32_t bits = x0 ^ x1;
        float f = __uint_as_float((bits >> 9) | 0x3f800000u) - 1.0f;
        const float lo = -0.99999994f;
        float u = __fadd_rn(__fmul_rn(f, 2.0f), lo);
        u = fmaxf(u, lo);
        sv[tid] = 1.41421356237f * erfinv_f32(u);
    }
    __syncthreads();
    if (tid < NDIR) {
        float a = sv[tid], b = sv[NDIR + tid], c = sv[2 * NDIR + tid];
        float n = sqrtf(a * a + b * b + c * c);
        n = fmaxf(n, 1e-12f);
        const float PRE = 8.0f * 1.4426950408889634f;  // 8*log2(e)
        sd[tid]            = (a / n) * PRE;
        sd[NDIR + tid]     = (b / n) * PRE;
        sd[2 * NDIR + tid] = (c / n) * PRE;
    }
    if (blockIdx.x == 0) {
        for (int i = tid; i < NE; i += 256) g_E[i] = 0.0f;
        if (tid == 0) g_done = 0u;
    }
    __syncthreads();
    int t64 = s_t64;
    int p = blockIdx.x * 256 + tid;

    // dw = softmax(pred) - onehot(tgt), channels 0,1, both batches
    float dw[2][2];
#pragma unroll
    for (int b = 0; b < 2; b++) {
        float x0 = pred[(b * 3 + 0) * PTOT + p];
        float x1 = pred[(b * 3 + 1) * PTOT + p];
        float x2 = pred[(b * 3 + 2) * PTOT + p];
        float m = fmaxf(x0, fmaxf(x1, x2));
        float e0 = expf(x0 - m), e1 = expf(x1 - m), e2 = expf(x2 - m);
        float s = e0 + e1 + e2;
        int tv;
        if (t64) tv = (int)((const long long*)tgt)[b * PTOT + p];
        else     tv = ((const int*)tgt)[b * PTOT + p];
        dw[b][0] = e0 / s - (tv == 0 ? 1.0f : 0.0f);
        dw[b][1] = e1 / s - (tv == 1 ? 1.0f : 0.0f);
    }

    if (p < PHALF) {
        // first half: duplicated pairs (positive)
        ulonglong2 d0, d1;
        d0.x = pack2(dw[0][0], dw[0][0]);
        d0.y = pack2(dw[0][1], dw[0][1]);
        d1.x = pack2(dw[1][0], dw[1][0]);
        d1.y = pack2(dw[1][1], dw[1][1]);
        g_dwd0[p] = d0;
        g_dwd1[p] = d1;

        // eb[d][p] = exp2(<coord_p, dir_d> * 8*log2e)
        int ix = p / 2304;
        int rem = p - ix * 2304;
        int iy = rem / 48;
        int iz = rem - iy * 48;
        const float CSTEP = 2.0f / 47.0f;
        float cx = fmaf((float)ix, CSTEP, -1.0f);
        float cy = fmaf((float)iy, CSTEP, -1.0f);
        float cz = fmaf((float)iz, CSTEP, -1.0f);
#pragma unroll
        for (int d = 0; d < NDIR; d++) {
            float nh = cx * sd[d];
            nh = fmaf(cy, sd[NDIR + d], nh);
            nh = fmaf(cz, sd[2 * NDIR + d], nh);
            g_eb[d * PHALF + p] = ex2_approx(nh);
        }
    } else {
        // second half: NEGATED duplicated pairs (for the -= accumulation)
        ulonglong2 n0, n1;
        n0.x = pack2(-dw[0][0], -dw[0][0]);
        n0.y = pack2(-dw[0][1], -dw[0][1]);
        n1.x = pack2(-dw[1][0], -dw[1][0]);
        n1.y = pack2(-dw[1][1], -dw[1][1]);
        g_dwn0[p] = n0;
        g_dwn1[p] = n1;

        // block-level partial sum of dw (constant term C), per-block slot
        s_red[tid] = make_float4(dw[0][0], dw[0][1], dw[1][0], dw[1][1]);
        __syncthreads();
        for (int off = 128; off > 0; off >>= 1) {
            if (tid < off) {
                float4 a = s_red[tid], b = s_red[tid + off];
                s_red[tid] = make_float4(a.x + b.x, a.y + b.y, a.z + b.z, a.w + b.w);
            }
            __syncthreads();
        }
        if (tid == 0) g_Cpart[blockIdx.x - 216] = s_red[0];
    }
}

// ---------------- kernel B: symmetric accumulation + fused final ------------
// block = (p-chunk of first half, d-group); warp = one direction;
// lane owns thresholds r0=2*lane, r1=2*lane+1 AND mirrors 63-r0, 63-r1.
__global__ __launch_bounds__(256, 4) void kernelB(float* __restrict__ out) {
    __shared__ float      s_eb[8][PCHUNK];   // 6 KB (reused as reduce scratch)
    __shared__ ulonglong2 s_lo0[PCHUNK];     // 3 KB  (dup b0c0, dup b0c1)
    __shared__ ulonglong2 s_lo1[PCHUNK];     // 3 KB  (dup b1c0, dup b1c1)
    __shared__ ulonglong2 s_hi0[PCHUNK];     // 3 KB  negated dups (antipode)
    __shared__ ulonglong2 s_hi1[PCHUNK];     // 3 KB
    __shared__ unsigned   s_ticket;

    int tid = threadIdx.x;
    int lane = tid & 31;
    int w = tid >> 5;
    int chunk = blockIdx.x >> 2;
    int dgroup = blockIdx.x & 3;
    int d = dgroup * 8 + w;
    int pbase = chunk * PCHUNK;
    int phibase = PTOT - 1 - pbase;           // antipode of pbase

    for (int j = tid; j < PCHUNK; j += 256) {
        s_lo0[j] = g_dwd0[pbase + j];
        s_lo1[j] = g_dwd1[pbase + j];
        s_hi0[j] = g_dwn0[phibase - j];
        s_hi1[j] = g_dwn1[phibase - j];
    }
    {
        const float4* src = (const float4*)(&g_eb[d * PHALF + pbase]);
        float4* dst = (float4*)(&s_eb[w][0]);
        for (int j = lane; j < PCHUNK / 4; j += 32) dst[j] = src[j];
    }

    // K = exp(-8*lin_r) for r0=2*lane, r1=2*lane+1
    float K0, K1;
    {
        double radius = 1.1 * sqrt(3.0);
        double step = 2.0 * radius / 63.0;
        K0 = (float)exp(-8.0 * (-radius + (double)(2 * lane) * step));
        K1 = (float)exp(-8.0 * (-radius + (double)(2 * lane + 1) * step));
    }
    __syncthreads();

    // packed accumulators over (r0, r1): pos for p, neg (pre-negated dw) for p-bar
    unsigned long long pos0 = 0ull, pos1 = 0ull, pos2 = 0ull, pos3 = 0ull;
    unsigned long long neg0 = 0ull, neg1 = 0ull, neg2 = 0ull, neg3 = 0ull;

    const float4* eb4p = (const float4*)(&s_eb[w][0]);

#define BODY(EB, I)                                    \
    {                                                  \
        float t0 = fmaf((EB), K0, 1.0f);               \
        float t1 = fmaf((EB), K1, 1.0f);               \
        float s0 = rcp_approx(t0);                     \
        float s1 = rcp_approx(t1);                     \
        unsigned long long s01 = pack2(s0, s1);        \
        ulonglong2 lo0 = s_lo0[I];                     \
        ulonglong2 lo1 = s_lo1[I];                     \
        ulonglong2 hi0 = s_hi0[I];                     \
        ulonglong2 hi1 = s_hi1[I];                     \
        fma2(pos0, lo0.x, s01);                        \
        fma2(pos1, lo0.y, s01);                        \
        fma2(pos2, lo1.x, s01);                        \
        fma2(pos3, lo1.y, s01);                        \
        fma2(neg0, hi0.x, s01);                        \
        fma2(neg1, hi0.y, s01);                        \
        fma2(neg2, hi1.x, s01);                        \
        fma2(neg3, hi1.y, s01);                        \
    }

#pragma unroll 2
    for (int j = 0; j < PCHUNK / 4; j++) {
        float4 eb4 = eb4p[j];
        BODY(eb4.x, 4 * j + 0)
        BODY(eb4.y, 4 * j + 1)
        BODY(eb4.z, 4 * j + 2)
        BODY(eb4.w, 4 * j + 3)
    }
#undef BODY

    // flush: pos -> (r0, r1); neg -> (63-r0, 63-r1)
    {
        int r0 = 2 * lane;
        int m0 = 63 - r0;       // mirror of r0
        float v0, v1;
        unpack2(pos0, v0, v1);
        atomicAdd(&g_E[0 * 2048 + d * NRES + r0],     v0);
        atomicAdd(&g_E[0 * 2048 + d * NRES + r0 + 1], v1);
        unpack2(pos1, v0, v1);
        atomicAdd(&g_E[1 * 2048 + d * NRES + r0],     v0);
        atomicAdd(&g_E[1 * 2048 + d * NRES + r0 + 1], v1);
        unpack2(pos2, v0, v1);
        atomicAdd(&g_E[2 * 2048 + d * NRES + r0],     v0);
        atomicAdd(&g_E[2 * 2048 + d * NRES + r0 + 1], v1);
        unpack2(pos3, v0, v1);
        atomicAdd(&g_E[3 * 2048 + d * NRES + r0],     v0);
        atomicAdd(&g_E[3 * 2048 + d * NRES + r0 + 1], v1);
        unpack2(neg0, v0, v1);
        atomicAdd(&g_E[0 * 2048 + d * NRES + m0],     v0);
        atomicAdd(&g_E[0 * 2048 + d * NRES + m0 - 1], v1);
        unpack2(neg1, v0, v1);
        atomicAdd(&g_E[1 * 2048 + d * NRES + m0],     v0);
        atomicAdd(&g_E[1 * 2048 + d * NRES + m0 - 1], v1);
        unpack2(neg2, v0, v1);
        atomicAdd(&g_E[2 * 2048 + d * NRES + m0],     v0);
        atomicAdd(&g_E[2 * 2048 + d * NRES + m0 - 1], v1);
        unpack2(neg3, v0, v1);
        atomicAdd(&g_E[3 * 2048 + d * NRES + m0],     v0);
        atomicAdd(&g_E[3 * 2048 + d * NRES + m0 - 1], v1);
    }

    // last block computes the final loss
    __threadfence();
    __syncthreads();
    if (tid == 0) s_ticket = atomicAdd(&g_done, 1u);
    __syncthreads();
    if (s_ticket != (unsigned)(NBLK_B - 1)) return;

    // constant term: C[bc] = sum over second-half p of dw[bc]
    // (reuse s_eb as reduce scratch -- main loop is done with it)
    float4* s_red = (float4*)&s_eb[0][0];
    {
        float4 c = make_float4(0.f, 0.f, 0.f, 0.f);
        if (tid < 216) c = g_Cpart[tid];
        s_red[tid] = c;
        __syncthreads();
        for (int off = 128; off > 0; off >>= 1) {
            if (tid < off) {
                float4 a = s_red[tid], b = s_red[tid + off];
                s_red[tid] = make_float4(a.x + b.x, a.y + b.y, a.z + b.z, a.w + b.w);
            }
            __syncthreads();
        }
    }
    float4 C = s_red[0];   // (b0c0, b0c1, b1c0, b1c1)

    float sum = 0.0f;
    for (int idx = tid; idx < 4096; idx += 256) {
        int b = idx >> 11;
        int dr = idx & 2047;
        float c0 = (b == 0) ? C.x : C.z;
        float c1 = (b == 0) ? C.y : C.w;
        float e0 = g_E[(b * 2 + 0) * 2048 + dr] + c0;
        float e1 = g_E[(b * 2 + 1) * 2048 + dr] + c1;
        float e2 = -(e0 + e1);                 // channel-2 by cancellation
        sum += e0 * e0 + e1 * e1 + e2 * e2;
    }
    __shared__ float red[8];
#pragma unroll
    for (int off = 16; off > 0; off >>= 1)
        sum += __shfl_down_sync(0xFFFFFFFFu, sum, off);
    if ((tid & 31) == 0) red[tid >> 5] = sum;
    __syncthreads();
    if (tid < 8) {
        float v = red[tid];
#pragma unroll
        for (int off = 4; off > 0; off >>= 1)
            v += __shfl_down_sync(0xFFu, v, off);
        if (tid == 0) out[0] = v / 12288.0f;
    }
}

// ---------------- launcher ---------------------------------------------------
extern "C" void kernel_launch(void* const* d_in, const int* in_sizes, int n_in,
                              void* d_out, int out_size) {
    const float* pred = (const float*)d_in[0];
    const void*  tgt  = d_in[1];
    float* out = (float*)d_out;
    (void)in_sizes; (void)n_in; (void)out_size;

    kernelA<<<NBLK_A, 256>>>(pred, tgt);
    kernelB<<<NBLK_B, 256>>>(out);
}

// round 15
// speedup vs baseline: 1.0804x; 1.0804x over previous
#include <cuda_runtime.h>
#include <cuda_bf16.h>
#include <cstdint>
#include <math.h>

#define PTOT     110592            // 48^3
#define PHALF    (PTOT / 2)        // 55296
#define NDIR     32
#define NRES     64
#define PCHUNK   384
#define NCHK     (PHALF / PCHUNK)  // 144
#define NBLK_B   (NCHK * 4)        // 576 (4 d-groups of 8 warps), ~1 wave
#define NBLK_A   (PTOT / 256)      // 432; blocks >= 216 are all-second-half
#define NE       (4 * NDIR * NRES) // 8192 floats

// ---------------- device scratch (static; no allocations) -------------------
__device__ float         g_E[NE];             // [(b*2+c)][d][r]
__device__ unsigned int  g_done;
__device__ float4        g_Cpart[216];        // per-block sums of dw, 2nd half
__device__ ulonglong2    g_dw[PTOT];          // .x=(b0c0,b1c0) .y=(b0c1,b1c1)
__device__ float         g_eb[NDIR * PHALF];  // eb[d][p] = exp(8*<coord_p,dir_d>)

// ---------------- asm helpers ------------------------------------------------
__device__ __forceinline__ unsigned long long pack2(float lo, float hi) {
    unsigned long long r;
    asm("mov.b64 %0, {%1, %2};" : "=l"(r) : "f"(lo), "f"(hi));
    return r;
}
__device__ __forceinline__ void unpack2(unsigned long long v, float& lo, float& hi) {
    asm("mov.b64 {%0, %1}, %2;" : "=f"(lo), "=f"(hi) : "l"(v));
}
__device__ __forceinline__ void fma2(unsigned long long& acc, unsigned long long ab,
                                     unsigned long long c) {
    asm("fma.rn.f32x2 %0, %1, %2, %0;" : "+l"(acc) : "l"(ab), "l"(c));
}
__device__ __forceinline__ float rcp_approx(float x) {
    float r;
    asm("rcp.approx.f32 %0, %1;" : "=f"(r) : "f"(x));
    return r;
}
__device__ __forceinline__ float ex2_approx(float x) {
    float r;
    asm("ex2.approx.f32 %0, %1;" : "=f"(r) : "f"(x));
    return r;
}

// ---------------- threefry2x32 (JAX partitionable path) ---------------------
__device__ __forceinline__ uint32_t rotl32(uint32_t x, int d) {
    return (x << d) | (x >> (32 - d));
}
__device__ void threefry2x32(uint32_t k0, uint32_t k1, uint32_t& x0, uint32_t& x1) {
    uint32_t k2 = k0 ^ k1 ^ 0x1BD11BDAu;
    x0 += k0; x1 += k1;
#define TFR(r) { x0 += x1; x1 = rotl32(x1, r); x1 ^= x0; }
    TFR(13) TFR(15) TFR(26) TFR(6)
    x0 += k1; x1 += k2 + 1u;
    TFR(17) TFR(29) TFR(16) TFR(24)
    x0 += k2; x1 += k0 + 2u;
    TFR(13) TFR(15) TFR(26) TFR(6)
    x0 += k0; x1 += k1 + 3u;
    TFR(17) TFR(29) TFR(16) TFR(24)
    x0 += k1; x1 += k2 + 4u;
    TFR(13) TFR(15) TFR(26) TFR(6)
    x0 += k2; x1 += k0 + 5u;
#undef TFR
}

__device__ float erfinv_f32(float x) {
    float w = -log1pf(-x * x);
    float p;
    if (w < 5.0f) {
        w = w - 2.5f;
        p =            2.81022636e-08f;
        p = fmaf(p, w, 3.43273939e-07f);
        p = fmaf(p, w, -3.5233877e-06f);
        p = fmaf(p, w, -4.39150654e-06f);
        p = fmaf(p, w, 0.00021858087f);
        p = fmaf(p, w, -0.00125372503f);
        p = fmaf(p, w, -0.00417768164f);
        p = fmaf(p, w, 0.246640727f);
        p = fmaf(p, w, 1.50140941f);
    } else {
        w = sqrtf(w) - 3.0f;
        p =            -0.000200214257f;
        p = fmaf(p, w, 0.000100950558f);
        p = fmaf(p, w, 0.00134934322f);
        p = fmaf(p, w, -0.00367342844f);
        p = fmaf(p, w, 0.00573950773f);
        p = fmaf(p, w, -0.0076224613f);
        p = fmaf(p, w, 0.00943887047f);
        p = fmaf(p, w, 1.00167406f);
        p = fmaf(p, w, 2.83297682f);
    }
    return p * x;
}

// ---------------- kernel A: init + prep + eb (first half only) --------------
__global__ __launch_bounds__(256) void kernelA(const float* __restrict__ pred,
                                               const void* __restrict__ tgt) {
    __shared__ float  sv[96];
    __shared__ float  sd[96];
    __shared__ int    s_t64;
    __shared__ float4 s_red[256];
    int tid = threadIdx.x;

    if (tid == 0) {
        // int64 targets (values 0..2, little-endian): odd 32-bit words all 0
        const int* ti = (const int*)tgt;
        int all0 = 1;
        for (int q = 0; q < 64; q++)
            if (ti[2 * q + 1] != 0) { all0 = 0; break; }
        s_t64 = all0;
    }
    if (tid < 96) {
        uint32_t x0 = 0u, x1 = (uint32_t)tid;
        threefry2x32(0u, 17u, x0, x1);
        uint32_t bits = x0 ^ x1;
        float f = __uint_as_float((bits >> 9) | 0x3f800000u) - 1.0f;
        const float lo = -0.99999994f;
        float u = __fadd_rn(__fmul_rn(f, 2.0f), lo);
        u = fmaxf(u, lo);
        sv[tid] = 1.41421356237f * erfinv_f32(u);
    }
    __syncthreads();
    if (tid < NDIR) {
        float a = sv[tid], b = sv[NDIR + tid], c = sv[2 * NDIR + tid];
        float n = sqrtf(a * a + b * b + c * c);
        n = fmaxf(n, 1e-12f);
        const float PRE = 8.0f * 1.4426950408889634f;  // 8*log2(e)
        sd[tid]            = (a / n) * PRE;
        sd[NDIR + tid]     = (b / n) * PRE;
        sd[2 * NDIR + tid] = (c / n) * PRE;
    }
    if (blockIdx.x == 0) {
        for (int i = tid; i < NE; i += 256) g_E[i] = 0.0f;
        if (tid == 0) g_done = 0u;
    }
    __syncthreads();
    int t64 = s_t64;
    int p = blockIdx.x * 256 + tid;

    // dw = softmax(pred) - onehot(tgt), channels 0,1, both batches
    float dw[2][2];
#pragma unroll
    for (int b = 0; b < 2; b++) {
        float x0 = pred[(b * 3 + 0) * PTOT + p];
        float x1 = pred[(b * 3 + 1) * PTOT + p];
        float x2 = pred[(b * 3 + 2) * PTOT + p];
        float m = fmaxf(x0, fmaxf(x1, x2));
        float e0 = expf(x0 - m), e1 = expf(x1 - m), e2 = expf(x2 - m);
        float s = e0 + e1 + e2;
        int tv;
        if (t64) tv = (int)((const long long*)tgt)[b * PTOT + p];
        else     tv = ((const int*)tgt)[b * PTOT + p];
        dw[b][0] = e0 / s - (tv == 0 ? 1.0f : 0.0f);
        dw[b][1] = e1 / s - (tv == 1 ? 1.0f : 0.0f);
    }
    // b-packed, non-duplicated: .x=(b0c0,b1c0), .y=(b0c1,b1c1)
    ulonglong2 o;
    o.x = pack2(dw[0][0], dw[1][0]);
    o.y = pack2(dw[0][1], dw[1][1]);
    g_dw[p] = o;

    if (p < PHALF) {
        // eb[d][p] = exp2(<coord_p, dir_d> * 8*log2e), first half only
        int ix = p / 2304;
        int rem = p - ix * 2304;
        int iy = rem / 48;
        int iz = rem - iy * 48;
        const float CSTEP = 2.0f / 47.0f;
        float cx = fmaf((float)ix, CSTEP, -1.0f);
        float cy = fmaf((float)iy, CSTEP, -1.0f);
        float cz = fmaf((float)iz, CSTEP, -1.0f);
#pragma unroll
        for (int d = 0; d < NDIR; d++) {
            float nh = cx * sd[d];
            nh = fmaf(cy, sd[NDIR + d], nh);
            nh = fmaf(cz, sd[2 * NDIR + d], nh);
            g_eb[d * PHALF + p] = ex2_approx(nh);
        }
    } else {
        // block-level partial sum of dw over second half (constant term C)
        s_red[tid] = make_float4(dw[0][0], dw[0][1], dw[1][0], dw[1][1]);
        __syncthreads();
        for (int off = 128; off > 0; off >>= 1) {
            if (tid < off) {
                float4 a = s_red[tid], b = s_red[tid + off];
                s_red[tid] = make_float4(a.x + b.x, a.y + b.y, a.z + b.z, a.w + b.w);
            }
            __syncthreads();
        }
        if (tid == 0) g_Cpart[blockIdx.x - 216] = s_red[0];
    }
}

// ---------------- kernel B: symmetric accumulation + fused final ------------
// block = (p-chunk of first half, d-group); warp = one direction;
// lane owns r0=2*lane, r1=2*lane+1 and mirrors 63-r0, 63-r1 (antipodes).
__global__ __launch_bounds__(256, 4) void kernelB(float* __restrict__ out) {
    __shared__ float      s_eb[8][PCHUNK];   // 12 KB (reused as reduce scratch)
    __shared__ ulonglong2 s_dwp[PCHUNK];     // 6 KB  p-side dw, b-packed
    __shared__ ulonglong2 s_dwn[PCHUNK];     // 6 KB  antipode dw, b-packed (+)
    __shared__ unsigned   s_ticket;

    int tid = threadIdx.x;
    int lane = tid & 31;
    int w = tid >> 5;
    int chunk = blockIdx.x >> 2;
    int dgroup = blockIdx.x & 3;
    int d = dgroup * 8 + w;
    int pbase = chunk * PCHUNK;
    int phibase = PTOT - 1 - pbase;           // antipode of pbase

    for (int j = tid; j < PCHUNK; j += 256) {
        s_dwp[j] = g_dw[pbase + j];
        s_dwn[j] = g_dw[phibase - j];
    }
    {
        const float4* src = (const float4*)(&g_eb[d * PHALF + pbase]);
        float4* dst = (float4*)(&s_eb[w][0]);
        for (int j = lane; j < PCHUNK / 4; j += 32) dst[j] = src[j];
    }

    // K = exp(-8*lin_r) for r0=2*lane, r1=2*lane+1
    float K0, K1;
    {
        double radius = 1.1 * sqrt(3.0);
        double step = 2.0 * radius / 63.0;
        K0 = (float)exp(-8.0 * (-radius + (double)(2 * lane) * step));
        K1 = (float)exp(-8.0 * (-radius + (double)(2 * lane + 1) * step));
    }
    __syncthreads();

    // accumulators pack (b0,b1); P* for p-side, N* for antipode (negated at flush)
    unsigned long long P0 = 0ull, P1 = 0ull, P2 = 0ull, P3 = 0ull;
    unsigned long long N0 = 0ull, N1 = 0ull, N2 = 0ull, N3 = 0ull;

    const float4* eb4p = (const float4*)(&s_eb[w][0]);

#define BODY(EB, I)                                    \
    {                                                  \
        float t0 = fmaf((EB), K0, 1.0f);               \
        float t1 = fmaf((EB), K1, 1.0f);               \
        float s0 = rcp_approx(t0);                     \
        float s1 = rcp_approx(t1);                     \
        unsigned long long s0d = pack2(s0, s0);        \
        unsigned long long s1d = pack2(s1, s1);        \
        ulonglong2 dp = s_dwp[I];                      \
        ulonglong2 dn = s_dwn[I];                      \
        fma2(P0, dp.x, s0d);   /* c0 @ r0 */           \
        fma2(P1, dp.x, s1d);   /* c0 @ r1 */           \
        fma2(P2, dp.y, s0d);   /* c1 @ r0 */           \
        fma2(P3, dp.y, s1d);   /* c1 @ r1 */           \
        fma2(N0, dn.x, s0d);                           \
        fma2(N1, dn.x, s1d);                           \
        fma2(N2, dn.y, s0d);                           \
        fma2(N3, dn.y, s1d);                           \
    }

#pragma unroll 2
    for (int j = 0; j < PCHUNK / 4; j++) {
        float4 eb4 = eb4p[j];
        BODY(eb4.x, 4 * j + 0)
        BODY(eb4.y, 4 * j + 1)
        BODY(eb4.z, 4 * j + 2)
        BODY(eb4.w, 4 * j + 3)
    }
#undef BODY

    // flush: P -> (r0, r1); N (negated) -> (63-r0, 63-r1)
    {
        int r0 = 2 * lane;
        int m0 = 63 - r0;       // mirror of r0
        float v0, v1;
        unpack2(P0, v0, v1);    // (b0c0, b1c0) @ r0
        atomicAdd(&g_E[0 * 2048 + d * NRES + r0], v0);
        atomicAdd(&g_E[2 * 2048 + d * NRES + r0], v1);
        unpack2(P1, v0, v1);    // @ r1
        atomicAdd(&g_E[0 * 2048 + d * NRES + r0 + 1], v0);
        atomicAdd(&g_E[2 * 2048 + d * NRES + r0 + 1], v1);
        unpack2(P2, v0, v1);    // (b0c1, b1c1) @ r0
        atomicAdd(&g_E[1 * 2048 + d * NRES + r0], v0);
        atomicAdd(&g_E[3 * 2048 + d * NRES + r0], v1);
        unpack2(P3, v0, v1);    // @ r1
        atomicAdd(&g_E[1 * 2048 + d * NRES + r0 + 1], v0);
        atomicAdd(&g_E[3 * 2048 + d * NRES + r0 + 1], v1);
        unpack2(N0, v0, v1);    // mirror, negated
        atomicAdd(&g_E[0 * 2048 + d * NRES + m0], -v0);
        atomicAdd(&g_E[2 * 2048 + d * NRES + m0], -v1);
        unpack2(N1, v0, v1);
        atomicAdd(&g_E[0 * 2048 + d * NRES + m0 - 1], -v0);
        atomicAdd(&g_E[2 * 2048 + d * NRES + m0 - 1], -v1);
        unpack2(N2, v0, v1);
        atomicAdd(&g_E[1 * 2048 + d * NRES + m0], -v0);
        atomicAdd(&g_E[3 * 2048 + d * NRES + m0], -v1);
        unpack2(N3, v0, v1);
        atomicAdd(&g_E[1 * 2048 + d * NRES + m0 - 1], -v0);
        atomicAdd(&g_E[3 * 2048 + d * NRES + m0 - 1], -v1);
    }

    // last block computes the final loss
    __threadfence();
    __syncthreads();
    if (tid == 0) s_ticket = atomicAdd(&g_done, 1u);
    __syncthreads();
    if (s_ticket != (unsigned)(NBLK_B - 1)) return;

    // constant term: C[bc] = sum over second-half p of dw[bc]
    // (reuse s_eb as reduce scratch -- main loop is done with it)
    float4* s_red = (float4*)&s_eb[0][0];
    {
        float4 c = make_float4(0.f, 0.f, 0.f, 0.f);
        if (tid < 216) c = g_Cpart[tid];
        s_red[tid] = c;
        __syncthreads();
        for (int off = 128; off > 0; off >>= 1) {
            if (tid < off) {
                float4 a = s_red[tid], b = s_red[tid + off];
                s_red[tid] = make_float4(a.x + b.x, a.y + b.y, a.z + b.z, a.w + b.w);
            }
            __syncthreads();
        }
    }
    float4 C = s_red[0];   // (b0c0, b0c1, b1c0, b1c1)

    float sum = 0.0f;
    for (int idx = tid; idx < 4096; idx += 256) {
        int b = idx >> 11;
        int dr = idx & 2047;
        float c0 = (b == 0) ? C.x : C.z;
        float c1 = (b == 0) ? C.y : C.w;
        float e0 = g_E[(b * 2 + 0) * 2048 + dr] + c0;
        float e1 = g_E[(b * 2 + 1) * 2048 + dr] + c1;
        float e2 = -(e0 + e1);                 // channel-2 by cancellation
        sum += e0 * e0 + e1 * e1 + e2 * e2;
    }
    __shared__ float red[8];
#pragma unroll
    for (int off = 16; off > 0; off >>= 1)
        sum += __shfl_down_sync(0xFFFFFFFFu, sum, off);
    if ((tid & 31) == 0) red[tid >> 5] = sum;
    __syncthreads();
    if (tid < 8) {
        float v = red[tid];
#pragma unroll
        for (int off = 4; off > 0; off >>= 1)
            v += __shfl_down_sync(0xFFu, v, off);
        if (tid == 0) out[0] = v / 12288.0f;
    }
}

// ---------------- launcher ---------------------------------------------------
extern "C" void kernel_launch(void* const* d_in, const int* in_sizes, int n_in,
                              void* d_out, int out_size) {
    const float* pred = (const float*)d_in[0];
    const void*  tgt  = d_in[1];
    float* out = (float*)d_out;
    (void)in_sizes; (void)n_in; (void)out_size;

    kernelA<<<NBLK_A, 256>>>(pred, tgt);
    kernelB<<<NBLK_B, 256>>>(out);
}